// round 4
// baseline (speedup 1.0000x reference)
#include <cuda_runtime.h>
#include <math.h>

#define Bdim 8
#define Tdim 2048
#define Ddim 256
#define CACT 64
#define CTIME 32
#define NCOL 96
#define NROWS (Bdim * Tdim)
#define LABEL_ID_ 3
#define ACT_START_ 4
#define TIME_START_ 68
#define VOCAB_ 100

#define GBLOCKS 128
#define GROWS 128
#define KHALF 128
#define SWSTR 98     // padded [d][c] weight stride: varies banks, 8B aligned
#define HSTR 132     // padded h row stride: float4-aligned, bank-varying

typedef unsigned long long ull;

// device scratch (static, no allocations)
__device__ float g_scr[(long)NROWS * NCOL];
__device__ unsigned char g_flags[NROWS];

__device__ __forceinline__ float softplusf(float x) { return log1pf(expf(x)); }

__device__ __forceinline__ ull splat2(float x) {
    ull r;
    asm("mov.b64 %0, {%1, %1};" : "=l"(r) : "r"(__float_as_uint(x)));
    return r;
}
__device__ __forceinline__ ull fma2(ull a, ull b, ull c) {
    ull d;
    asm("fma.rn.f32x2 %0, %1, %2, %3;" : "=l"(d) : "l"(a), "l"(b), "l"(c));
    return d;
}

// ---------------------------------------------------------------------------
// Fat kernel: blocks 0..127 = GEMM role, blocks 128..143 = proto role.
// Roles are independent (proto -> scratch+flags), so they run concurrently.
// ---------------------------------------------------------------------------
__global__ void __launch_bounds__(512, 1) fat_kernel(
    const int* __restrict__ tokens, const float* __restrict__ h,
    const float* __restrict__ E,
    const float* __restrict__ Wn, const float* __restrict__ bn,
    const float* __restrict__ Wt, const float* __restrict__ bt,
    const float* __restrict__ tsa, const float* __restrict__ tst,
    const float* __restrict__ psa, const float* __restrict__ pst,
    const float* __restrict__ ppa, const float* __restrict__ ppt,
    const float* __restrict__ pta, const float* __restrict__ ptt,
    float* __restrict__ out)
{
    extern __shared__ float sm[];
    int tid = threadIdx.x;

    if (blockIdx.x < GBLOCKS) {
        // =================== GEMM role ===================
        float* sW = sm;                       // KHALF * SWSTR
        float* hs = sm + KHALF * SWSTR;       // GROWS * HSTR
        float* bs = hs + GROWS * HSTR;        // NCOL

        float s_ta = softplusf(*tsa);
        float s_tt = softplusf(*tst);
        if (tid < NCOL) bs[tid] = (tid < CACT) ? bn[tid] : bt[tid - CACT];

        ull acc[12];
#pragma unroll
        for (int i = 0; i < 12; ++i) acc[i] = 0ull;

        long rowbase = (long)blockIdx.x * GROWS;
        const float4* gh = (const float4*)h;

        for (int stage = 0; stage < 2; ++stage) {
            __syncthreads();
            // ---- fold weights: sW[d][c] = W[c][d] + s*E[row_c][d] ----
            {
                float4 wv[6], evv[6];
#pragma unroll
                for (int k = 0; k < 6; ++k) {
                    int i = tid + 512 * k;
                    int c = i % 96, d4 = i / 96;
                    const float* wrow; int erow;
                    if (c < CACT) { wrow = Wn + c * Ddim; erow = ACT_START_ + c; }
                    else          { wrow = Wt + (c - CACT) * Ddim; erow = TIME_START_ + (c - CACT); }
                    wv[k]  = ((const float4*)wrow)[stage * 32 + d4];
                    evv[k] = ((const float4*)(E + (long)erow * Ddim))[stage * 32 + d4];
                }
#pragma unroll
                for (int k = 0; k < 6; ++k) {
                    int i = tid + 512 * k;
                    int c = i % 96, d4 = i / 96;
                    float sc = (c < CACT) ? s_ta : s_tt;
                    float* p = sW + c;
                    int db = 4 * d4;
                    p[(db + 0) * SWSTR] = wv[k].x + sc * evv[k].x;
                    p[(db + 1) * SWSTR] = wv[k].y + sc * evv[k].y;
                    p[(db + 2) * SWSTR] = wv[k].z + sc * evv[k].z;
                    p[(db + 3) * SWSTR] = wv[k].w + sc * evv[k].w;
                }
            }
            // ---- stage h half ----
#pragma unroll
            for (int it = 0; it < 8; ++it) {
                int i = tid + 512 * it;
                int r = i >> 5, d4 = i & 31;
                float4 v = gh[(rowbase + r) * (Ddim / 4) + stage * (KHALF / 4) + d4];
                *(float4*)(hs + r * HSTR + 4 * d4) = v;
            }
            __syncthreads();

            // ---- compute: 2 rows x 12 cols per thread, packed fp32x2 FMA ----
            int cx = tid & 7;      // 8 col groups * 12
            int rx = tid >> 3;     // 64 row groups * 2
            const float* hp = hs + (rx * 2) * HSTR;
            const float* wp = sW + cx * 12;
#pragma unroll 4
            for (int d = 0; d < KHALF; ++d) {
                const ull* wrow = (const ull*)(wp + d * SWSTR);
                ull w0 = wrow[0], w1 = wrow[1], w2 = wrow[2];
                ull w3 = wrow[3], w4 = wrow[4], w5 = wrow[5];
                ull s0 = splat2(hp[d]);
                ull s1 = splat2(hp[HSTR + d]);
                acc[0]  = fma2(w0, s0, acc[0]);  acc[1]  = fma2(w1, s0, acc[1]);
                acc[2]  = fma2(w2, s0, acc[2]);  acc[3]  = fma2(w3, s0, acc[3]);
                acc[4]  = fma2(w4, s0, acc[4]);  acc[5]  = fma2(w5, s0, acc[5]);
                acc[6]  = fma2(w0, s1, acc[6]);  acc[7]  = fma2(w1, s1, acc[7]);
                acc[8]  = fma2(w2, s1, acc[8]);  acc[9]  = fma2(w3, s1, acc[9]);
                acc[10] = fma2(w4, s1, acc[10]); acc[11] = fma2(w5, s1, acc[11]);
            }
        }

        // ---- store ----
        int cx = tid & 7;
        int rx = tid >> 3;
        float* outT = out + (long)NROWS * CACT;
#pragma unroll
        for (int j = 0; j < 2; ++j) {
            long row = rowbase + rx * 2 + j;
#pragma unroll
            for (int i = 0; i < 6; ++i) {
                union { ull u; float2 f; } u;
                u.u = acc[j * 6 + i];
                int c0 = cx * 12 + 2 * i;
                float v0 = u.f.x + bs[c0];
                float v1 = u.f.y + bs[c0 + 1];
                if (c0 < CACT) out[row * CACT + c0] = v0;
                else           outT[row * CTIME + (c0 - CACT)] = v0;
                if (c0 + 1 < CACT) out[row * CACT + c0 + 1] = v1;
                else               outT[row * CTIME + (c0 + 1 - CACT)] = v1;
            }
        }
    } else {
        // =================== proto role ===================
        int pb = blockIdx.x - GBLOCKS;       // 0..15
        int b = pb >> 1;
        int kind = pb & 1;                   // 0 = act, 1 = time
        int C  = kind ? CTIME : CACT;
        int lo = kind ? TIME_START_ : ACT_START_;
        int hi = kind ? VOCAB_ : TIME_START_;

        float* q    = sm;                     // CACT*Ddim reserved
        float* hn   = sm + CACT * Ddim;       // 256
        float* red  = hn + Ddim;              // 16
        float* n2   = red + 16;               // 64
        int*   ev_t = (int*)(n2 + 64);        // 2048
        int*   ev_n = ev_t + Tdim;            // 2048
        int*   toks = ev_n + Tdim;            // 2048
        __shared__ int s_nev;
        __shared__ float s_dq;

        int wid = tid >> 5, lane = tid & 31;

        for (int i = tid; i < Tdim; i += 512) toks[i] = tokens[(long)b * Tdim + i];
        __syncthreads();

        if (wid == 0) {
            int cnt = 0;
            for (int ch = 0; ch < Tdim / 32; ++ch) {
                int t = ch * 32 + lane;
                bool isl = (toks[t] == LABEL_ID_);
                unsigned m = __ballot_sync(0xffffffffu, isl);
                if (isl) {
                    int idx = cnt + __popc(m & ((1u << lane) - 1u));
                    ev_t[idx] = t;
                    ev_n[idx] = toks[(t + 1) & (Tdim - 1)];
                }
                cnt += __popc(m);
            }
            if (lane == 0) s_nev = cnt;
        }
        if (kind == 0) {
            for (int i = tid; i < Tdim; i += 512)
                g_flags[b * Tdim + i] = (toks[i] == LABEL_ID_) ? 1 : 0;
        }

        float alpha = softplusf(kind ? *ppt : *ppa);
        float scale = softplusf(kind ? *pst : *psa) * softplusf(kind ? *ptt : *pta);

        // init q rows = alpha * normalized E class rows (warp per row)
        for (int r = wid; r < C; r += 16) {
            int erow = (kind ? TIME_START_ : ACT_START_) + r;
            const float* e = E + (long)erow * Ddim;
            float v[8]; float ss = 0.f;
#pragma unroll
            for (int k = 0; k < 8; ++k) { v[k] = e[lane + 32 * k]; ss += v[k] * v[k]; }
#pragma unroll
            for (int o = 16; o > 0; o >>= 1) ss += __shfl_xor_sync(0xffffffffu, ss, o);
            float inv = alpha / fmaxf(sqrtf(ss), 1e-12f);
#pragma unroll
            for (int k = 0; k < 8; ++k) q[r * Ddim + lane + 32 * k] = v[k] * inv;
        }
        if (tid < C) n2[tid] = alpha * alpha;
        __syncthreads();

        int nev = s_nev;
        const float* hb = h + (long)b * Tdim * Ddim;
        float* scr = g_scr + (long)b * Tdim * NCOL + (kind ? CACT : 0);

        int cnt = 0;
        float hv = 0.f;
        if (nev > 0 && tid < Ddim) hv = hb[(long)ev_t[0] * Ddim + tid];

        for (int e = 0; e < nev; ++e) {
            int t = ev_t[e], ntok = ev_n[e];

            // ---- normalize h row ----
            if (tid < Ddim) {
                float ss = hv * hv;
#pragma unroll
                for (int o = 16; o > 0; o >>= 1) ss += __shfl_xor_sync(0xffffffffu, ss, o);
                if (lane == 0) red[wid] = ss;
            }
            __syncthreads();
            if (tid == 0) {
                float s = 0.f;
#pragma unroll
                for (int i = 0; i < 8; ++i) s += red[i];
                float inv = 1.0f / fmaxf(sqrtf(s), 1e-12f);
                red[8] = inv;
                red[9] = s * inv * inv;     // |hn|^2
            }
            __syncthreads();
            if (tid < Ddim) hn[tid] = hv * red[8];
            __syncthreads();
            float hn2 = red[9];
            if (tid < Ddim && e + 1 < nev) hv = hb[(long)ev_t[e + 1] * Ddim + tid];

            bool sup = (ntok >= lo) && (ntok < hi);
            int cls = ntok - lo;

            // ---- sims: lane-parallel partial dots, bank-rotated ----
            if (!kind) {
                int c = tid >> 3, seg = tid & 7;
                const float* qc = q + c * Ddim + seg * 32;
                const float* hc = hn + seg * 32;
                float s1 = 0.f;
#pragma unroll
                for (int i = 0; i < 32; ++i) {
                    int dd = (i + lane) & 31;
                    s1 += qc[dd] * hc[dd];
                }
#pragma unroll
                for (int o = 1; o < 8; o <<= 1) s1 += __shfl_xor_sync(0xffffffffu, s1, o);
                if (seg == 0) {
                    if (sup && c == cls) s_dq = s1;
                    float val = (cnt > 0) ? scale * s1 * rsqrtf(n2[c]) : 0.f;
                    scr[(long)t * NCOL + c] = val;
                }
            } else {
                int c = tid >> 4, seg = tid & 15;
                const float* qc = q + c * Ddim + seg * 16;
                const float* hc = hn + seg * 16;
                float s1 = 0.f;
#pragma unroll
                for (int i = 0; i < 16; ++i) {
                    int dd = (i + (lane >> 1)) & 15;
                    s1 += qc[dd] * hc[dd];
                }
#pragma unroll
                for (int o = 1; o < 16; o <<= 1) s1 += __shfl_xor_sync(0xffffffffu, s1, o);
                if (seg == 0) {
                    if (sup && c == cls) s_dq = s1;
                    float val = (cnt > 0) ? scale * s1 * rsqrtf(n2[c]) : 0.f;
                    scr[(long)t * NCOL + c] = val;
                }
            }
            __syncthreads();   // q reads + s_dq write done

            if (sup) {
                if (tid < Ddim) q[cls * Ddim + tid] += hn[tid];
                if (tid == 0) n2[cls] += 2.f * s_dq + hn2;
                cnt++;
            }
            __syncthreads();
        }
    }
}

// ---------------------------------------------------------------------------
// Epilogue: add proto scratch into out at flagged (label) rows.
// ---------------------------------------------------------------------------
__global__ void __launch_bounds__(512) epi_kernel(float* __restrict__ out)
{
    int row = blockIdx.x * 512 + threadIdx.x;
    if (g_flags[row]) {
        const float* s = g_scr + (long)row * NCOL;
        float* oa = out + (long)row * CACT;
#pragma unroll
        for (int c = 0; c < CACT; ++c) oa[c] += s[c];
        float* ot = out + (long)NROWS * CACT + (long)row * CTIME;
#pragma unroll
        for (int c = 0; c < CTIME; ++c) ot[c] += s[CACT + c];
    }
}

// ---------------------------------------------------------------------------
extern "C" void kernel_launch(void* const* d_in, const int* in_sizes, int n_in,
                              void* d_out, int out_size)
{
    const int*   tokens = (const int*)d_in[0];
    const float* h      = (const float*)d_in[1];
    const float* E      = (const float*)d_in[2];
    const float* Wn     = (const float*)d_in[3];
    const float* bn     = (const float*)d_in[4];
    const float* Wt     = (const float*)d_in[5];
    const float* bt     = (const float*)d_in[6];

    size_t smem = (size_t)(KHALF * SWSTR + GROWS * HSTR + NCOL) * sizeof(float);
    cudaFuncSetAttribute(fat_kernel, cudaFuncAttributeMaxDynamicSharedMemorySize, (int)smem);

    fat_kernel<<<GBLOCKS + 16, 512, smem>>>(
        tokens, h, E, Wn, bn, Wt, bt,
        (const float*)d_in[7],  (const float*)d_in[8],
        (const float*)d_in[9],  (const float*)d_in[10],
        (const float*)d_in[11], (const float*)d_in[12],
        (const float*)d_in[13], (const float*)d_in[14],
        (float*)d_out);

    epi_kernel<<<NROWS / 512, 512>>>((float*)d_out);
}

// round 5
// speedup vs baseline: 1.6700x; 1.6700x over previous
#include <cuda_runtime.h>
#include <math.h>

#define Tdim 2048
#define Ddim 256
#define CACT 64
#define CTIME 32
#define NROWS (8 * 2048)
#define LABEL_ID_ 3

#define SW4N (96 * 33)     // float4 slots for weights [c][33]
#define HS4N (128 * 33)    // float4 slots for h tile  [r][33]
#define OBSTR 98

typedef unsigned long long ull;

__device__ float g_scr[(long)NROWS * 96];
__device__ int   g_evt[8 * Tdim];
__device__ int   g_nev[8];

union U4 { float4 f; ull u[2]; };

__device__ __forceinline__ float softplusf(float x) { return log1pf(expf(x)); }
__device__ __forceinline__ ull fma2(ull a, ull b, ull c) {
    ull d; asm("fma.rn.f32x2 %0,%1,%2,%3;" : "=l"(d) : "l"(a), "l"(b), "l"(c)); return d;
}

__global__ void __launch_bounds__(256, 1) fat_kernel(
    const int* __restrict__ tokens, const float* __restrict__ h,
    const float* __restrict__ E,
    const float* __restrict__ Wn, const float* __restrict__ bn,
    const float* __restrict__ Wt, const float* __restrict__ bt,
    const float* __restrict__ tsa, const float* __restrict__ tst,
    const float* __restrict__ psa, const float* __restrict__ pst,
    const float* __restrict__ ppa, const float* __restrict__ ppt,
    const float* __restrict__ pta, const float* __restrict__ ptt,
    float* __restrict__ out)
{
    extern __shared__ float sm[];
    int tid = threadIdx.x, lane = tid & 31, wid = tid >> 5;
    int bx = blockIdx.x;

    if (bx >= 24) {
        // ====================== GEMM role ======================
        float4* sW4 = (float4*)sm;            // [c][33] per K-stage
        float4* hs4 = sW4 + SW4N;             // [r][33] per K-stage
        float*  ob  = (float*)hs4;            // output staging (reuse)

        int cg = wid;
        long rowbase = (long)(bx - 24) * 128;
        float s_ta = softplusf(*tsa), s_tt = softplusf(*tst);

        float bsv[12];
#pragma unroll
        for (int j = 0; j < 12; ++j) {
            int c = cg * 12 + j;
            bsv[j] = (c < CACT) ? bn[c] : bt[c - CACT];
        }

        ull acc[4][12];
#pragma unroll
        for (int r = 0; r < 4; ++r)
#pragma unroll
            for (int j = 0; j < 12; ++j) acc[r][j] = 0ull;

        const float4* gh = (const float4*)h;

        for (int stage = 0; stage < 2; ++stage) {
            __syncthreads();
            // fold weights: sW4[c][d4] = W[c] + s*E[class(c)]  (warp per c)
#pragma unroll
            for (int k = 0; k < 12; ++k) {
                int i = tid + 256 * k;
                int c = i >> 5, d4 = i & 31;
                const float4* w4 = (const float4*)((c < CACT) ? (Wn + c * Ddim)
                                                              : (Wt + (c - CACT) * Ddim));
                int erow = (c < CACT) ? (4 + c) : (68 + (c - CACT));
                float sc = (c < CACT) ? s_ta : s_tt;
                float4 w = w4[stage * 32 + d4];
                float4 e = ((const float4*)(E + (long)erow * Ddim))[stage * 32 + d4];
                sW4[c * 33 + d4] = make_float4(w.x + sc * e.x, w.y + sc * e.y,
                                               w.z + sc * e.z, w.w + sc * e.w);
            }
            // stage h half
#pragma unroll
            for (int k = 0; k < 16; ++k) {
                int i = tid + 256 * k;
                int r = i >> 5, d4 = i & 31;
                hs4[r * 33 + d4] = gh[(rowbase + r) * 64 + stage * 32 + d4];
            }
            __syncthreads();

            const float4* wb = sW4 + cg * 12 * 33;
#pragma unroll 2
            for (int chunk = 0; chunk < 32; ++chunk) {
                U4 hv[4];
#pragma unroll
                for (int r = 0; r < 4; ++r) hv[r].f = hs4[(lane + 32 * r) * 33 + chunk];
#pragma unroll
                for (int g = 0; g < 2; ++g) {
                    U4 wv[6];
#pragma unroll
                    for (int j = 0; j < 6; ++j) wv[j].f = wb[(g * 6 + j) * 33 + chunk];
#pragma unroll
                    for (int r = 0; r < 4; ++r)
#pragma unroll
                        for (int j = 0; j < 6; ++j)
                            acc[r][g * 6 + j] = fma2(wv[j].u[0], hv[r].u[0], acc[r][g * 6 + j]);
#pragma unroll
                    for (int r = 0; r < 4; ++r)
#pragma unroll
                        for (int j = 0; j < 6; ++j)
                            acc[r][g * 6 + j] = fma2(wv[j].u[1], hv[r].u[1], acc[r][g * 6 + j]);
                }
            }
        }

        // epilogue: horizontal add + bias -> smem stage -> coalesced stores
        __syncthreads();
#pragma unroll
        for (int r = 0; r < 4; ++r) {
            int row = lane + 32 * r;
#pragma unroll
            for (int j = 0; j < 12; ++j) {
                union { ull u; float2 f; } v; v.u = acc[r][j];
                ob[row * OBSTR + cg * 12 + j] = v.f.x + v.f.y + bsv[j];
            }
        }
        __syncthreads();
        float* outT = out + (long)NROWS * CACT;
#pragma unroll
        for (int k = 0; k < 16; ++k) {              // act: 4096 float2
            int i = tid + 256 * k;
            int r = i >> 5, c2 = i & 31;
            float2 v = *(float2*)(ob + r * OBSTR + 2 * c2);
            *(float2*)(out + (rowbase + r) * CACT + 2 * c2) = v;
        }
#pragma unroll
        for (int k = 0; k < 8; ++k) {               // time: 2048 float2
            int i = tid + 256 * k;
            int r = i >> 4, c2 = i & 15;
            float2 v = *(float2*)(ob + r * OBSTR + CACT + 2 * c2);
            *(float2*)(outT + (rowbase + r) * CTIME + 2 * c2) = v;
        }
    } else {
        // ====================== proto role ======================
        int b = bx / 3, part = bx % 3;
        int clo = (part == 0) ? 4 : (part == 1) ? 36 : 68;
        int klo = (part == 2) ? 68 : 4;
        int khi = (part == 2) ? 100 : 68;
        int cbase = part * 32;

        float* q    = sm;                    // 32 x 256
        float* hn   = q + 32 * Ddim;         // 256
        float* red  = hn + Ddim;             // 8
        float* n2   = red + 8;               // 32
        int*   ev_t = (int*)(n2 + 32);       // 2048
        int*   ev_n = ev_t + Tdim;           // 2048
        int*   toks = ev_n + Tdim;           // 2048
        __shared__ int s_nev;
        __shared__ float s_dq;

        for (int i = tid; i < Tdim; i += 256) toks[i] = tokens[(long)b * Tdim + i];
        __syncthreads();

        if (wid == 0) {
            int cnt = 0;
            for (int ch = 0; ch < Tdim / 32; ++ch) {
                int t = ch * 32 + lane;
                bool isl = (toks[t] == LABEL_ID_);
                unsigned m = __ballot_sync(0xffffffffu, isl);
                if (isl) {
                    int idx = cnt + __popc(m & ((1u << lane) - 1u));
                    ev_t[idx] = t;
                    ev_n[idx] = toks[(t + 1) & (Tdim - 1)];
                    if (part == 0) g_evt[b * Tdim + idx] = t;
                }
                cnt += __popc(m);
            }
            if (lane == 0) { s_nev = cnt; if (part == 0) g_nev[b] = cnt; }
        }

        float alpha = softplusf(part == 2 ? *ppt : *ppa);
        float scale = softplusf(part == 2 ? *pst : *psa) * softplusf(part == 2 ? *ptt : *pta);

        // q[c] = alpha * l2norm(E[clo + c])   (warp per class)
        for (int c = wid; c < 32; c += 8) {
            const float* e = E + (long)(clo + c) * Ddim;
            float v[8]; float ss = 0.f;
#pragma unroll
            for (int k = 0; k < 8; ++k) { v[k] = e[lane + 32 * k]; ss += v[k] * v[k]; }
#pragma unroll
            for (int o = 16; o > 0; o >>= 1) ss += __shfl_xor_sync(0xffffffffu, ss, o);
            float inv = alpha / fmaxf(sqrtf(ss), 1e-12f);
#pragma unroll
            for (int k = 0; k < 8; ++k) q[c * Ddim + lane + 32 * k] = v[k] * inv;
        }
        if (tid < 32) n2[tid] = alpha * alpha;
        __syncthreads();

        int nev = s_nev;
        const float* hb = h + (long)b * Tdim * Ddim;
        int cnt = 0;
        float hv = (nev > 0) ? hb[(long)ev_t[0] * Ddim + tid] : 0.f;

        for (int e = 0; e < nev; ++e) {
            int t = ev_t[e], ntok = ev_n[e];

            float ss = hv * hv;
#pragma unroll
            for (int o = 16; o > 0; o >>= 1) ss += __shfl_xor_sync(0xffffffffu, ss, o);
            if (lane == 0) red[wid] = ss;
            __syncthreads();                                   // (1)
            float tot = red[0] + red[1] + red[2] + red[3]
                      + red[4] + red[5] + red[6] + red[7];
            float inv = 1.0f / fmaxf(sqrtf(tot), 1e-12f);
            float hn2 = tot * inv * inv;
            hn[tid] = hv * inv;
            __syncthreads();                                   // (2)
            if (e + 1 < nev) hv = hb[(long)ev_t[e + 1] * Ddim + tid];

            bool supk = (ntok >= klo) && (ntok < khi);
            bool supm = (ntok >= clo) && (ntok < clo + 32);
            int cls = ntok - clo;

            int c = tid >> 3, seg = tid & 7;
            const float* qc = q + c * Ddim + seg * 32;
            const float* hc = hn + seg * 32;
            float s1 = 0.f;
#pragma unroll
            for (int i = 0; i < 32; ++i) {
                int dd = (i + lane) & 31;
                s1 += qc[dd] * hc[dd];
            }
#pragma unroll
            for (int o = 1; o < 8; o <<= 1) s1 += __shfl_xor_sync(0xffffffffu, s1, o);
            if (seg == 0) {
                if (supm && c == cls) s_dq = s1;
                float val = (cnt > 0) ? scale * s1 * rsqrtf(n2[c]) : 0.f;
                g_scr[((long)b * Tdim + t) * 96 + cbase + c] = val;
            }
            __syncthreads();                                   // (3)

            if (supm) {
                q[cls * Ddim + tid] += hn[tid];
                if (tid == 0) n2[cls] += 2.f * s_dq + hn2;
            }
            if (supk) cnt++;
        }
    }
}

// Epilogue: add proto sims into out at label rows (event-list driven).
__global__ void __launch_bounds__(128) epi_kernel(float* __restrict__ out)
{
    int b = blockIdx.x >> 3, sub = blockIdx.x & 7;
    int c = threadIdx.x;
    if (c >= 96) return;
    int nev = g_nev[b];
    float* outT = out + (long)NROWS * CACT;
    for (int e = sub; e < nev; e += 8) {
        long row = (long)b * Tdim + g_evt[b * Tdim + e];
        float v = g_scr[row * 96 + c];
        if (c < CACT) out[row * CACT + c] += v;
        else          outT[row * CTIME + (c - CACT)] += v;
    }
}

extern "C" void kernel_launch(void* const* d_in, const int* in_sizes, int n_in,
                              void* d_out, int out_size)
{
    size_t smem = (size_t)(SW4N + HS4N) * 16;
    cudaFuncSetAttribute(fat_kernel, cudaFuncAttributeMaxDynamicSharedMemorySize, (int)smem);

    fat_kernel<<<152, 256, smem>>>(
        (const int*)d_in[0], (const float*)d_in[1], (const float*)d_in[2],
        (const float*)d_in[3], (const float*)d_in[4],
        (const float*)d_in[5], (const float*)d_in[6],
        (const float*)d_in[7], (const float*)d_in[8],
        (const float*)d_in[9], (const float*)d_in[10],
        (const float*)d_in[11], (const float*)d_in[12],
        (const float*)d_in[13], (const float*)d_in[14],
        (float*)d_out);

    epi_kernel<<<64, 128>>>((float*)d_out);
}